// round 3
// baseline (speedup 1.0000x reference)
#include <cuda_runtime.h>
#include <math.h>

#define BGRAPH  32768
#define NPG     54
#define EPG     144
#define NTOT    (BGRAPH*NPG)
#define ETOT    (BGRAPH*EPG)
#define OSTRIDE 232            // 226 used, padded to multiple of 8

// Scratch for concat([embeds(216), g(10)]) per graph.
__device__ __align__(16) float g_scratch[(size_t)BGRAPH * OSTRIDE];

// ---------- packed fp32x2 helpers (FFMA2 path, sm_103a) ----------
__device__ __forceinline__ void ffma2(unsigned long long& d,
                                      unsigned long long a,
                                      unsigned long long b) {
    asm("fma.rn.f32x2 %0, %1, %2, %0;" : "+l"(d) : "l"(a), "l"(b));
}
__device__ __forceinline__ unsigned long long pack2(float lo, float hi) {
    unsigned long long r;
    asm("mov.b64 %0, {%1, %2};" : "=l"(r) : "f"(lo), "f"(hi));
    return r;
}
__device__ __forceinline__ void unpack2(float& lo, float& hi, unsigned long long v) {
    asm("mov.b64 {%0, %1}, %2;" : "=f"(lo), "=f"(hi) : "l"(v));
}

// ============================================================================
// Kernel 1: one CTA per graph. Entire GNN in shared memory.
// Weight smem layout (floats):
//   WT1 (16 rows j, stride 20, k=0..7 rel1 / 8..15 root1) : 0..319
//   b1: 320..335
//   WT2 (4 rows j, stride 36, k=0..15 rel2 / 16..31 root2): 336..479
//   b2: 480..483
//   Wg1 484  bg1 564  Wg2 572  bg2 636  Wg3 644  bg3 724   (total 734)
// ============================================================================
__global__ void __launch_bounds__(128) gnn_kernel(
    const float* __restrict__ x,  const int* __restrict__ ei,
    const float* __restrict__ ea, const float* __restrict__ gf,
    const float* __restrict__ Wrel1, const float* __restrict__ b1,
    const float* __restrict__ Wroot1,
    const float* __restrict__ Wrel2, const float* __restrict__ b2,
    const float* __restrict__ Wroot2,
    const float* __restrict__ Wg1, const float* __restrict__ bg1,
    const float* __restrict__ Wg2, const float* __restrict__ bg2,
    const float* __restrict__ Wg3, const float* __restrict__ bg3)
{
    __shared__ __align__(16) float sx[NPG * 8];     // node features, row-major
    __shared__ __align__(16) float sagg1[NPG * 8];  // conv1 aggregate
    __shared__ __align__(16) float sh1[NPG * 16];   // hidden layer 1
    __shared__ __align__(16) float sagg2[NPG * 16]; // conv2 aggregate
    __shared__ float tattr[EPG];
    __shared__ int   tsrc[EPG];
    __shared__ int   tdst[EPG];
    __shared__ float sattrS[EPG];                   // sorted by dst
    __shared__ int   ssrcS[EPG];
    __shared__ int   scnt[NPG];
    __shared__ int   sstart[NPG];
    __shared__ int   scur[NPG];
    __shared__ __align__(16) float sW[734];
    __shared__ float sgf[10];

    const int b   = blockIdx.x;
    const int tid = threadIdx.x;
    const int nbase = b * NPG;
    const int ebase = b * EPG;

    // ---- phase 0: zero counts + weights (transposed, padded) ----
    if (tid < NPG) scnt[tid] = 0;
    #pragma unroll
    for (int i = tid; i < 256; i += 128) {          // WT1
        int j = i >> 4, k = i & 15;
        sW[j * 20 + k] = (k < 8) ? Wrel1[k * 16 + j] : Wroot1[(k - 8) * 16 + j];
    }
    if (tid < 16) sW[320 + tid] = b1[tid];
    {                                               // WT2
        int j = tid >> 5, k = tid & 31;
        sW[336 + j * 36 + k] = (k < 16) ? Wrel2[k * 4 + j] : Wroot2[(k - 16) * 4 + j];
    }
    if (tid < 4)  sW[480 + tid] = b2[tid];
    if (tid < 80) sW[484 + tid] = Wg1[tid];
    if (tid < 8)  sW[564 + tid] = bg1[tid];
    if (tid < 64) sW[572 + tid] = Wg2[tid];
    if (tid < 8)  sW[636 + tid] = bg2[tid];
    if (tid < 80) sW[644 + tid] = Wg3[tid];
    if (tid < 10) sW[724 + tid] = bg3[tid];
    if (tid < 10) sgf[tid] = gf[b * 10 + tid];
    __syncthreads();

    // ---- phase 1: stage edges, count degrees, load x ----
    {
        const float* xg = x + (size_t)nbase * 8;
        for (int i = tid; i < NPG * 8; i += 128) sx[i] = xg[i];
        for (int e = tid; e < EPG; e += 128) {
            int s = ei[ebase + e] - nbase;
            int d = ei[ETOT + ebase + e] - nbase;
            tsrc[e] = s; tdst[e] = d; tattr[e] = ea[ebase + e];
            atomicAdd(&scnt[d], 1);
        }
    }
    __syncthreads();

    // ---- phase 2: exclusive prefix over 54 counts (warp 0) ----
    if (tid < 32) {
        int c0 = scnt[tid];
        int c1 = (tid + 32 < NPG) ? scnt[tid + 32] : 0;
        int v0 = c0, v1 = c1;
        #pragma unroll
        for (int o = 1; o < 32; o <<= 1) {
            int t = __shfl_up_sync(0xffffffffu, v0, o); if (tid >= o) v0 += t;
        }
        int tot0 = __shfl_sync(0xffffffffu, v0, 31);
        #pragma unroll
        for (int o = 1; o < 32; o <<= 1) {
            int t = __shfl_up_sync(0xffffffffu, v1, o); if (tid >= o) v1 += t;
        }
        int s0 = v0 - c0;
        int s1 = tot0 + v1 - c1;
        sstart[tid] = s0; scur[tid] = s0;
        if (tid + 32 < NPG) { sstart[tid + 32] = s1; scur[tid + 32] = s1; }
    }
    __syncthreads();

    // ---- phase 3: scatter edges into CSR order ----
    for (int e = tid; e < EPG; e += 128) {
        int d = tdst[e];
        int p = atomicAdd(&scur[d], 1);
        ssrcS[p]  = tsrc[e];
        sattrS[p] = tattr[e];
    }
    __syncthreads();

    // ---- conv1 aggregation: agg1[d][0:8] = sum attr * x[src] (f32x2) ----
    if (tid < NPG * 2) {
        int d = tid >> 1, c = tid & 1;
        unsigned long long a0 = 0ull, a1 = 0ull;
        int beg = sstart[d], end = beg + scnt[d];
        for (int p = beg; p < end; p++) {
            unsigned long long ap = pack2(sattrS[p], sattrS[p]);
            ulonglong2 v = *reinterpret_cast<const ulonglong2*>(sx + ssrcS[p] * 8 + c * 4);
            ffma2(a0, v.x, ap); ffma2(a1, v.y, ap);
        }
        ulonglong2 r; r.x = a0; r.y = a1;
        *reinterpret_cast<ulonglong2*>(sagg1 + d * 8 + c * 4) = r;
    }
    __syncthreads();

    // ---- lin1: h1 = relu(agg1 @ Wrel1 + b1 + x @ Wroot1)  [54x16] ----
    for (int i = tid; i < NPG * 16; i += 128) {
        int n = i >> 4, j = i & 15;
        const ulonglong2* ar = reinterpret_cast<const ulonglong2*>(sagg1 + n * 8);
        const ulonglong2* xr = reinterpret_cast<const ulonglong2*>(sx + n * 8);
        const ulonglong2* wr = reinterpret_cast<const ulonglong2*>(sW + j * 20);
        unsigned long long acc = 0ull;
        ulonglong2 w0 = wr[0], w1 = wr[1], w2 = wr[2], w3 = wr[3];
        ulonglong2 aa0 = ar[0], aa1 = ar[1], xx0 = xr[0], xx1 = xr[1];
        ffma2(acc, aa0.x, w0.x); ffma2(acc, aa0.y, w0.y);
        ffma2(acc, aa1.x, w1.x); ffma2(acc, aa1.y, w1.y);
        ffma2(acc, xx0.x, w2.x); ffma2(acc, xx0.y, w2.y);
        ffma2(acc, xx1.x, w3.x); ffma2(acc, xx1.y, w3.y);
        float lo, hi; unpack2(lo, hi, acc);
        sh1[i] = fmaxf(lo + hi + sW[320 + j], 0.f);
    }
    __syncthreads();

    // ---- conv2 aggregation: agg2[d][0:16] = sum attr * h1[src] (f32x2) ----
    for (int i = tid; i < NPG * 4; i += 128) {
        int d = i >> 2, c = i & 3;
        unsigned long long a0 = 0ull, a1 = 0ull;
        int beg = sstart[d], end = beg + scnt[d];
        for (int p = beg; p < end; p++) {
            unsigned long long ap = pack2(sattrS[p], sattrS[p]);
            ulonglong2 v = *reinterpret_cast<const ulonglong2*>(sh1 + ssrcS[p] * 16 + c * 4);
            ffma2(a0, v.x, ap); ffma2(a1, v.y, ap);
        }
        ulonglong2 r; r.x = a0; r.y = a1;
        *reinterpret_cast<ulonglong2*>(sagg2 + d * 16 + c * 4) = r;
    }
    __syncthreads();

    float* og = g_scratch + (size_t)b * OSTRIDE;

    if (tid < 32) {
        // ---- warp 0: global MLP 10 -> 8 -> 8 -> 10 via shuffles ----
        int lane = tid;
        int l8  = lane & 7;
        int l10 = (lane < 10) ? lane : 0;
        float a1v = sW[564 + l8];
        #pragma unroll
        for (int k = 0; k < 10; k++) a1v += sgf[k] * sW[484 + k * 8 + l8];
        float s1 = fmaxf(a1v, 0.f);

        float a2v = sW[636 + l8];
        #pragma unroll
        for (int k = 0; k < 8; k++)
            a2v += __shfl_sync(0xffffffffu, s1, k) * sW[572 + k * 8 + l8];
        float s2 = fmaxf(a2v, 0.f);

        float a3v = sW[724 + l10];
        #pragma unroll
        for (int k = 0; k < 8; k++)
            a3v += __shfl_sync(0xffffffffu, s2, k) * sW[644 + k * 10 + l10];
        if (lane < 10) og[216 + lane] = fmaxf(a3v, 0.f);
    } else {
        // ---- warps 1-3: lin2 (f32x2) -> write embeds [54x4] to scratch ----
        for (int i = tid - 32; i < NPG * 4; i += 96) {
            int n = i >> 2, j = i & 3;
            const ulonglong2* ar = reinterpret_cast<const ulonglong2*>(sagg2 + n * 16);
            const ulonglong2* hr = reinterpret_cast<const ulonglong2*>(sh1 + n * 16);
            const ulonglong2* wr = reinterpret_cast<const ulonglong2*>(sW + 336 + j * 36);
            unsigned long long acc = 0ull;
            ulonglong2 w, v;
            w = wr[0]; v = ar[0]; ffma2(acc, v.x, w.x); ffma2(acc, v.y, w.y);
            w = wr[1]; v = ar[1]; ffma2(acc, v.x, w.x); ffma2(acc, v.y, w.y);
            w = wr[2]; v = ar[2]; ffma2(acc, v.x, w.x); ffma2(acc, v.y, w.y);
            w = wr[3]; v = ar[3]; ffma2(acc, v.x, w.x); ffma2(acc, v.y, w.y);
            w = wr[4]; v = hr[0]; ffma2(acc, v.x, w.x); ffma2(acc, v.y, w.y);
            w = wr[5]; v = hr[1]; ffma2(acc, v.x, w.x); ffma2(acc, v.y, w.y);
            w = wr[6]; v = hr[2]; ffma2(acc, v.x, w.x); ffma2(acc, v.y, w.y);
            w = wr[7]; v = hr[3]; ffma2(acc, v.x, w.x); ffma2(acc, v.y, w.y);
            float lo, hi; unpack2(lo, hi, acc);
            og[i] = fmaxf(lo + hi + sW[480 + j], 0.f);
        }
    }
}

// ============================================================================
// Kernel 2: batched out-MLP. 32 graphs per CTA, 256 threads.
// Thread = (half, column j): column j of Wo1 for 16 graphs.
// ============================================================================
__global__ void __launch_bounds__(256) mlp_kernel(
    const float* __restrict__ Wo1, const float* __restrict__ bo1,
    const float* __restrict__ Wo2, const float* __restrict__ bo2,
    float* __restrict__ out)
{
    __shared__ __align__(16) float sG[32 * OSTRIDE];   // 29,696 B (reused for reduce)
    __shared__ float sRed[8][32];

    const int tid  = threadIdx.x;
    const int j    = tid & 127;
    const int half = tid >> 7;          // 0: graphs 0-15, 1: graphs 16-31
    const int b0   = blockIdx.x * 32;

    // stage 32 rows of scratch (layout identical -> straight linear copy)
    {
        const float4* src4 = reinterpret_cast<const float4*>(g_scratch) + (size_t)b0 * (OSTRIDE / 4);
        float4* dst4 = reinterpret_cast<float4*>(sG);
        for (int i = tid; i < 32 * (OSTRIDE / 4); i += 256) dst4[i] = src4[i];
    }
    __syncthreads();

    unsigned long long acc[16];
    #pragma unroll
    for (int g = 0; g < 16; g++) acc[g] = 0ull;

    const float* wcol  = Wo1 + j;              // column j of [226,128]
    const float* gbase = sG + half * 16 * OSTRIDE;

    for (int kc = 0; kc < 224; kc += 8) {
        float w0 = wcol[(kc + 0) * 128], w1 = wcol[(kc + 1) * 128];
        float w2 = wcol[(kc + 2) * 128], w3 = wcol[(kc + 3) * 128];
        float w4 = wcol[(kc + 4) * 128], w5 = wcol[(kc + 5) * 128];
        float w6 = wcol[(kc + 6) * 128], w7 = wcol[(kc + 7) * 128];
        unsigned long long wp0 = pack2(w0, w1), wp1 = pack2(w2, w3);
        unsigned long long wp2 = pack2(w4, w5), wp3 = pack2(w6, w7);
        #pragma unroll
        for (int g = 0; g < 16; g++) {
            const ulonglong2* p = reinterpret_cast<const ulonglong2*>(gbase + g * OSTRIDE + kc);
            ulonglong2 va = p[0];
            ulonglong2 vb = p[1];
            ffma2(acc[g], va.x, wp0);
            ffma2(acc[g], va.y, wp1);
            ffma2(acc[g], vb.x, wp2);
            ffma2(acc[g], vb.y, wp3);
        }
    }
    {   // tail: k = 224, 225
        unsigned long long wp = pack2(wcol[224 * 128], wcol[225 * 128]);
        #pragma unroll
        for (int g = 0; g < 16; g++) {
            unsigned long long v = *reinterpret_cast<const unsigned long long*>(gbase + g * OSTRIDE + 224);
            ffma2(acc[g], v, wp);
        }
    }

    const float bj   = bo1[j];
    const float w2j  = Wo2[j];
    const float bo2v = bo2[0];

    __syncthreads();   // done reading sG; reuse for partial products
    #pragma unroll
    for (int g = 0; g < 16; g++) {
        float lo, hi; unpack2(lo, hi, acc[g]);
        float p = fmaxf(lo + hi + bj, 0.f) * w2j;
        sG[j * 33 + half * 16 + g] = p;       // [128][33] region, conflict-free
    }
    __syncthreads();

    {   // reduce over j: 8 chunks of 16 columns each
        int g = tid & 31, q = tid >> 5;
        float s = 0.f;
        #pragma unroll
        for (int jj = 0; jj < 16; jj++) s += sG[(q * 16 + jj) * 33 + g];
        sRed[q][g] = s;
    }
    __syncthreads();
    if (tid < 32) {
        float z = sRed[0][tid] + sRed[1][tid] + sRed[2][tid] + sRed[3][tid]
                + sRed[4][tid] + sRed[5][tid] + sRed[6][tid] + sRed[7][tid] + bo2v;
        out[b0 + tid] = 1.f / (1.f + expf(-z));
    }
}

// ============================================================================
extern "C" void kernel_launch(void* const* d_in, const int* in_sizes, int n_in,
                              void* d_out, int out_size) {
    (void)in_sizes; (void)n_in; (void)out_size;
    const float* x      = (const float*)d_in[0];
    const int*   ei     = (const int*)  d_in[1];
    const float* ea     = (const float*)d_in[2];
    const float* gfeats = (const float*)d_in[3];
    const float* Wrel1  = (const float*)d_in[4];
    const float* b1     = (const float*)d_in[5];
    const float* Wroot1 = (const float*)d_in[6];
    const float* Wrel2  = (const float*)d_in[7];
    const float* b2     = (const float*)d_in[8];
    const float* Wroot2 = (const float*)d_in[9];
    const float* Wg1    = (const float*)d_in[10];
    const float* bg1    = (const float*)d_in[11];
    const float* Wg2    = (const float*)d_in[12];
    const float* bg2    = (const float*)d_in[13];
    const float* Wg3    = (const float*)d_in[14];
    const float* bg3    = (const float*)d_in[15];
    const float* Wo1    = (const float*)d_in[16];
    const float* bo1    = (const float*)d_in[17];
    const float* Wo2    = (const float*)d_in[18];
    const float* bo2    = (const float*)d_in[19];
    float* out = (float*)d_out;

    gnn_kernel<<<BGRAPH, 128>>>(x, ei, ea, gfeats,
                                Wrel1, b1, Wroot1, Wrel2, b2, Wroot2,
                                Wg1, bg1, Wg2, bg2, Wg3, bg3);
    mlp_kernel<<<BGRAPH / 32, 256>>>(Wo1, bo1, Wo2, bo2, out);
}

// round 4
// speedup vs baseline: 1.1915x; 1.1915x over previous
#include <cuda_runtime.h>
#include <math.h>
#include <stdint.h>

#define BGRAPH  32768
#define NPG     54
#define EPG     144
#define NTOT    (BGRAPH*NPG)
#define ETOT    (BGRAPH*EPG)
#define OSTRIDE 232            // 226 used, padded
#define GNN_GRID 1184          // 8 * 148: one wave on GB300

// Scratch for concat([embeds(216), g(10)]) per graph.
__device__ __align__(16) float g_scratch[(size_t)BGRAPH * OSTRIDE];
// Packed/transposed weights, written once by prep_kernel.
__device__ __align__(16) float g_wblob[736];

// ---------- packed fp32x2 helpers ----------
__device__ __forceinline__ void ffma2(unsigned long long& d,
                                      unsigned long long a,
                                      unsigned long long b) {
    asm("fma.rn.f32x2 %0, %1, %2, %0;" : "+l"(d) : "l"(a), "l"(b));
}
__device__ __forceinline__ unsigned long long pack2(float lo, float hi) {
    unsigned long long r;
    asm("mov.b64 %0, {%1, %2};" : "=l"(r) : "f"(lo), "f"(hi));
    return r;
}
__device__ __forceinline__ void unpack2(float& lo, float& hi, unsigned long long v) {
    asm("mov.b64 {%0, %1}, %2;" : "=f"(lo), "=f"(hi) : "l"(v));
}

// ---------- cp.async helpers ----------
__device__ __forceinline__ uint32_t smem_u32(const void* p) {
    return (uint32_t)__cvta_generic_to_shared(p);
}
__device__ __forceinline__ void cpa16(uint32_t s, const void* g) {
    asm volatile("cp.async.cg.shared.global [%0], [%1], 16;" :: "r"(s), "l"(g));
}
__device__ __forceinline__ void cpa4(uint32_t s, const void* g) {
    asm volatile("cp.async.ca.shared.global [%0], [%1], 4;" :: "r"(s), "l"(g));
}
__device__ __forceinline__ void cpa_commit() {
    asm volatile("cp.async.commit_group;");
}
__device__ __forceinline__ void cpa_wait0() {
    asm volatile("cp.async.wait_group 0;");
}
__device__ __forceinline__ void cpa_wait1() {
    asm volatile("cp.async.wait_group 1;");
}

// ============================================================================
// Prep kernel: pack + transpose all small weights into g_wblob (once).
//  WT1 (16 rows j, stride 20; k 0..7 = rel1, 8..15 = root1) : 0..319
//  b1: 320   WT2 (4 rows j, stride 36; k 0..15 rel2, 16..31 root2): 336..479
//  b2: 480   Wg1 484  bg1 564  Wg2 572  bg2 636  Wg3 644  bg3 724
// ============================================================================
__global__ void prep_kernel(
    const float* __restrict__ Wrel1, const float* __restrict__ b1,
    const float* __restrict__ Wroot1,
    const float* __restrict__ Wrel2, const float* __restrict__ b2,
    const float* __restrict__ Wroot2,
    const float* __restrict__ Wg1, const float* __restrict__ bg1,
    const float* __restrict__ Wg2, const float* __restrict__ bg2,
    const float* __restrict__ Wg3, const float* __restrict__ bg3)
{
    int t = threadIdx.x;   // 256
    {   // WT1
        int j = t >> 4, k = t & 15;
        g_wblob[j * 20 + k] = (k < 8) ? Wrel1[k * 16 + j] : Wroot1[(k - 8) * 16 + j];
    }
    if (t < 16) g_wblob[320 + t] = b1[t];
    if (t < 128) {  // WT2
        int j = t >> 5, k = t & 31;
        g_wblob[336 + j * 36 + k] = (k < 16) ? Wrel2[k * 4 + j] : Wroot2[(k - 16) * 4 + j];
    }
    if (t < 4)  g_wblob[480 + t] = b2[t];
    if (t < 80) g_wblob[484 + t] = Wg1[t];
    if (t < 8)  g_wblob[564 + t] = bg1[t];
    if (t < 64) g_wblob[572 + t] = Wg2[t];
    if (t < 8)  g_wblob[636 + t] = bg2[t];
    if (t < 80) g_wblob[644 + t] = Wg3[t];
    if (t < 10) g_wblob[724 + t] = bg3[t];
}

// ============================================================================
// Kernel 1: persistent CTAs, grid-stride over graphs, cp.async double buffer.
// Buf layout (floats): x:0(432) src:432(144) dst:576(144) ea:720(144) gf:864(12)
// ============================================================================
#define BUF_F   880
#define BUF_X   0
#define BUF_SRC 432
#define BUF_DST 576
#define BUF_EA  720
#define BUF_GF  864

__global__ void __launch_bounds__(128, 8) gnn_kernel(
    const float* __restrict__ x,  const int* __restrict__ ei,
    const float* __restrict__ ea, const float* __restrict__ gf)
{
    __shared__ __align__(16) float sW[736];
    __shared__ __align__(16) float sh1[NPG * 16];
    __shared__ __align__(16) float sagg1[NPG * 8];
    __shared__ __align__(16) float sagg2[NPG * 16];
    __shared__ int   shead[NPG];
    __shared__ int   snext[EPG];
    __shared__ int   ssrc[EPG];
    __shared__ __align__(16) float buf[2][BUF_F];

    const int tid = threadIdx.x;

    // ---- load packed weights once per CTA ----
    for (int i = tid; i < 736; i += 128) sW[i] = g_wblob[i];
    if (tid < NPG) shead[tid] = -1;

    // ---- prefetch first graph ----
    int g0 = blockIdx.x;
    {
        uint32_t base = smem_u32(&buf[0][0]);
        const float* xg = x + (size_t)g0 * (NPG * 8);
        const int*   sg = ei + (size_t)g0 * EPG;
        const int*   dg = ei + (size_t)ETOT + (size_t)g0 * EPG;
        const float* eg = ea + (size_t)g0 * EPG;
        for (int i = tid; i < 216; i += 128) {
            if (i < 108)      cpa16(base + (BUF_X * 4)   + i * 16,        xg + i * 4);
            else if (i < 144) cpa16(base + (BUF_SRC * 4) + (i - 108) * 16, sg + (i - 108) * 4);
            else if (i < 180) cpa16(base + (BUF_DST * 4) + (i - 144) * 16, dg + (i - 144) * 4);
            else              cpa16(base + (BUF_EA * 4)  + (i - 180) * 16, eg + (i - 180) * 4);
        }
        if (tid < 10) cpa4(base + (BUF_GF + tid) * 4, gf + (size_t)g0 * 10 + tid);
    }
    cpa_commit();

    int cur = 0;
    for (int g = g0; g < BGRAPH; g += GNN_GRID) {
        int gn = g + GNN_GRID;
        if (gn < BGRAPH) {       // prefetch next into other buffer
            uint32_t base = smem_u32(&buf[cur ^ 1][0]);
            const float* xg = x + (size_t)gn * (NPG * 8);
            const int*   sg = ei + (size_t)gn * EPG;
            const int*   dg = ei + (size_t)ETOT + (size_t)gn * EPG;
            const float* eg = ea + (size_t)gn * EPG;
            for (int i = tid; i < 216; i += 128) {
                if (i < 108)      cpa16(base + (BUF_X * 4)   + i * 16,        xg + i * 4);
                else if (i < 144) cpa16(base + (BUF_SRC * 4) + (i - 108) * 16, sg + (i - 108) * 4);
                else if (i < 180) cpa16(base + (BUF_DST * 4) + (i - 144) * 16, dg + (i - 144) * 4);
                else              cpa16(base + (BUF_EA * 4)  + (i - 180) * 16, eg + (i - 180) * 4);
            }
            if (tid < 10) cpa4(base + (BUF_GF + tid) * 4, gf + (size_t)gn * 10 + tid);
            cpa_commit();
            cpa_wait1();         // current buffer complete, next may be in flight
        } else {
            cpa_wait0();
        }
        __syncthreads();         // buffer + shead init visible

        const float* bx  = &buf[cur][BUF_X];
        const int*   bs  = (const int*)&buf[cur][BUF_SRC];
        const int*   bd  = (const int*)&buf[cur][BUF_DST];
        const float* bea = &buf[cur][BUF_EA];
        const float* bgf = &buf[cur][BUF_GF];
        const int nbase = g * NPG;

        // ---- build per-destination edge linked lists ----
        for (int e = tid; e < EPG; e += 128) {
            int d = bd[e] - nbase;
            ssrc[e]  = bs[e] - nbase;
            snext[e] = atomicExch(&shead[d], e);
        }
        __syncthreads();

        // ---- conv1 agg: agg1[d][0:8] = sum attr * x[src] ----
        if (tid < NPG * 2) {
            int d = tid >> 1, c = tid & 1;
            unsigned long long a0 = 0ull, a1 = 0ull;
            for (int e = shead[d]; e >= 0; e = snext[e]) {
                unsigned long long ap = pack2(bea[e], bea[e]);
                ulonglong2 v = *reinterpret_cast<const ulonglong2*>(bx + ssrc[e] * 8 + c * 4);
                ffma2(a0, v.x, ap); ffma2(a1, v.y, ap);
            }
            ulonglong2 r; r.x = a0; r.y = a1;
            *reinterpret_cast<ulonglong2*>(sagg1 + d * 8 + c * 4) = r;
        }
        __syncthreads();

        // ---- lin1: h1 = relu(agg1 @ Wrel1 + b1 + x @ Wroot1) ----
        for (int i = tid; i < NPG * 16; i += 128) {
            int n = i >> 4, j = i & 15;
            const ulonglong2* ar = reinterpret_cast<const ulonglong2*>(sagg1 + n * 8);
            const ulonglong2* xr = reinterpret_cast<const ulonglong2*>(bx + n * 8);
            const ulonglong2* wr = reinterpret_cast<const ulonglong2*>(sW + j * 20);
            unsigned long long acc = 0ull;
            ulonglong2 w0 = wr[0], w1 = wr[1], w2 = wr[2], w3 = wr[3];
            ulonglong2 aa0 = ar[0], aa1 = ar[1], xx0 = xr[0], xx1 = xr[1];
            ffma2(acc, aa0.x, w0.x); ffma2(acc, aa0.y, w0.y);
            ffma2(acc, aa1.x, w1.x); ffma2(acc, aa1.y, w1.y);
            ffma2(acc, xx0.x, w2.x); ffma2(acc, xx0.y, w2.y);
            ffma2(acc, xx1.x, w3.x); ffma2(acc, xx1.y, w3.y);
            float lo, hi; unpack2(lo, hi, acc);
            sh1[i] = fmaxf(lo + hi + sW[320 + j], 0.f);
        }
        __syncthreads();

        // ---- conv2 agg: agg2[d][0:16] = sum attr * h1[src] ----
        for (int i = tid; i < NPG * 4; i += 128) {
            int d = i >> 2, c = i & 3;
            unsigned long long a0 = 0ull, a1 = 0ull;
            for (int e = shead[d]; e >= 0; e = snext[e]) {
                unsigned long long ap = pack2(bea[e], bea[e]);
                ulonglong2 v = *reinterpret_cast<const ulonglong2*>(sh1 + ssrc[e] * 16 + c * 4);
                ffma2(a0, v.x, ap); ffma2(a1, v.y, ap);
            }
            ulonglong2 r; r.x = a0; r.y = a1;
            *reinterpret_cast<ulonglong2*>(sagg2 + d * 16 + c * 4) = r;
        }
        __syncthreads();

        float* og = g_scratch + (size_t)g * OSTRIDE;

        if (tid < 32) {
            // ---- warp 0: global MLP 10 -> 8 -> 8 -> 10 via shuffles ----
            int lane = tid;
            int l8  = lane & 7;
            int l10 = (lane < 10) ? lane : 0;
            float a1v = sW[564 + l8];
            #pragma unroll
            for (int k = 0; k < 10; k++) a1v += bgf[k] * sW[484 + k * 8 + l8];
            float s1 = fmaxf(a1v, 0.f);

            float a2v = sW[636 + l8];
            #pragma unroll
            for (int k = 0; k < 8; k++)
                a2v += __shfl_sync(0xffffffffu, s1, k) * sW[572 + k * 8 + l8];
            float s2 = fmaxf(a2v, 0.f);

            float a3v = sW[724 + l10];
            #pragma unroll
            for (int k = 0; k < 8; k++)
                a3v += __shfl_sync(0xffffffffu, s2, k) * sW[644 + k * 10 + l10];
            if (lane < 10) og[216 + lane] = fmaxf(a3v, 0.f);
        } else {
            // re-init shead for next graph (hidden under lin2)
            if (tid - 32 < NPG) shead[tid - 32] = -1;
            // ---- warps 1-3: lin2 -> embeds [54x4] to scratch ----
            for (int i = tid - 32; i < NPG * 4; i += 96) {
                int n = i >> 2, j = i & 3;
                const ulonglong2* ar = reinterpret_cast<const ulonglong2*>(sagg2 + n * 16);
                const ulonglong2* hr = reinterpret_cast<const ulonglong2*>(sh1 + n * 16);
                const ulonglong2* wr = reinterpret_cast<const ulonglong2*>(sW + 336 + j * 36);
                unsigned long long acc = 0ull;
                ulonglong2 w, v;
                w = wr[0]; v = ar[0]; ffma2(acc, v.x, w.x); ffma2(acc, v.y, w.y);
                w = wr[1]; v = ar[1]; ffma2(acc, v.x, w.x); ffma2(acc, v.y, w.y);
                w = wr[2]; v = ar[2]; ffma2(acc, v.x, w.x); ffma2(acc, v.y, w.y);
                w = wr[3]; v = ar[3]; ffma2(acc, v.x, w.x); ffma2(acc, v.y, w.y);
                w = wr[4]; v = hr[0]; ffma2(acc, v.x, w.x); ffma2(acc, v.y, w.y);
                w = wr[5]; v = hr[1]; ffma2(acc, v.x, w.x); ffma2(acc, v.y, w.y);
                w = wr[6]; v = hr[2]; ffma2(acc, v.x, w.x); ffma2(acc, v.y, w.y);
                w = wr[7]; v = hr[3]; ffma2(acc, v.x, w.x); ffma2(acc, v.y, w.y);
                float lo, hi; unpack2(lo, hi, acc);
                og[i] = fmaxf(lo + hi + sW[480 + j], 0.f);
            }
        }
        __syncthreads();   // compute done before next prefetch overwrites buf[cur]
        cur ^= 1;
    }
}

// ============================================================================
// Kernel 2: batched out-MLP. 32 graphs per CTA, 256 threads, 4 CTAs/SM.
// ============================================================================
__global__ void __launch_bounds__(256, 4) mlp_kernel(
    const float* __restrict__ Wo1, const float* __restrict__ bo1,
    const float* __restrict__ Wo2, const float* __restrict__ bo2,
    float* __restrict__ out)
{
    __shared__ __align__(16) float sG[32 * OSTRIDE];   // 29,696 B (reused for reduce)
    __shared__ float sRed[8][32];

    const int tid  = threadIdx.x;
    const int j    = tid & 127;
    const int half = tid >> 7;          // 0: graphs 0-15, 1: graphs 16-31
    const int b0   = blockIdx.x * 32;

    // stage 32 rows of scratch via cp.async
    {
        uint32_t base = smem_u32(sG);
        const float* src = g_scratch + (size_t)b0 * OSTRIDE;
        for (int i = tid; i < 32 * (OSTRIDE / 4); i += 256)
            cpa16(base + i * 16, src + i * 4);
        cpa_commit();
        cpa_wait0();
    }
    __syncthreads();

    unsigned long long acc[16];
    #pragma unroll
    for (int g = 0; g < 16; g++) acc[g] = 0ull;

    const float* wcol  = Wo1 + j;              // column j of [226,128]
    const float* gbase = sG + half * 16 * OSTRIDE;

    for (int kc = 0; kc < 224; kc += 8) {
        float w0 = wcol[(kc + 0) * 128], w1 = wcol[(kc + 1) * 128];
        float w2 = wcol[(kc + 2) * 128], w3 = wcol[(kc + 3) * 128];
        float w4 = wcol[(kc + 4) * 128], w5 = wcol[(kc + 5) * 128];
        float w6 = wcol[(kc + 6) * 128], w7 = wcol[(kc + 7) * 128];
        unsigned long long wp0 = pack2(w0, w1), wp1 = pack2(w2, w3);
        unsigned long long wp2 = pack2(w4, w5), wp3 = pack2(w6, w7);
        #pragma unroll
        for (int g = 0; g < 16; g++) {
            const ulonglong2* p = reinterpret_cast<const ulonglong2*>(gbase + g * OSTRIDE + kc);
            ulonglong2 va = p[0];
            ulonglong2 vb = p[1];
            ffma2(acc[g], va.x, wp0);
            ffma2(acc[g], va.y, wp1);
            ffma2(acc[g], vb.x, wp2);
            ffma2(acc[g], vb.y, wp3);
        }
    }
    {   // tail: k = 224, 225
        unsigned long long wp = pack2(wcol[224 * 128], wcol[225 * 128]);
        #pragma unroll
        for (int g = 0; g < 16; g++) {
            unsigned long long v = *reinterpret_cast<const unsigned long long*>(gbase + g * OSTRIDE + 224);
            ffma2(acc[g], v, wp);
        }
    }

    const float bj   = bo1[j];
    const float w2j  = Wo2[j];
    const float bo2v = bo2[0];

    __syncthreads();   // done reading sG; reuse for partial products
    #pragma unroll
    for (int g = 0; g < 16; g++) {
        float lo, hi; unpack2(lo, hi, acc[g]);
        float p = fmaxf(lo + hi + bj, 0.f) * w2j;
        sG[j * 33 + half * 16 + g] = p;       // [128][33] region, conflict-free
    }
    __syncthreads();

    {   // reduce over j: 8 chunks of 16 columns each
        int g = tid & 31, q = tid >> 5;
        float s = 0.f;
        #pragma unroll
        for (int jj = 0; jj < 16; jj++) s += sG[(q * 16 + jj) * 33 + g];
        sRed[q][g] = s;
    }
    __syncthreads();
    if (tid < 32) {
        float z = sRed[0][tid] + sRed[1][tid] + sRed[2][tid] + sRed[3][tid]
                + sRed[4][tid] + sRed[5][tid] + sRed[6][tid] + sRed[7][tid] + bo2v;
        out[b0 + tid] = 1.f / (1.f + expf(-z));
    }
}

// ============================================================================
extern "C" void kernel_launch(void* const* d_in, const int* in_sizes, int n_in,
                              void* d_out, int out_size) {
    (void)in_sizes; (void)n_in; (void)out_size;
    const float* x      = (const float*)d_in[0];
    const int*   ei     = (const int*)  d_in[1];
    const float* ea     = (const float*)d_in[2];
    const float* gfeats = (const float*)d_in[3];
    const float* Wrel1  = (const float*)d_in[4];
    const float* b1     = (const float*)d_in[5];
    const float* Wroot1 = (const float*)d_in[6];
    const float* Wrel2  = (const float*)d_in[7];
    const float* b2     = (const float*)d_in[8];
    const float* Wroot2 = (const float*)d_in[9];
    const float* Wg1    = (const float*)d_in[10];
    const float* bg1    = (const float*)d_in[11];
    const float* Wg2    = (const float*)d_in[12];
    const float* bg2    = (const float*)d_in[13];
    const float* Wg3    = (const float*)d_in[14];
    const float* bg3    = (const float*)d_in[15];
    const float* Wo1    = (const float*)d_in[16];
    const float* bo1    = (const float*)d_in[17];
    const float* Wo2    = (const float*)d_in[18];
    const float* bo2    = (const float*)d_in[19];
    float* out = (float*)d_out;

    prep_kernel<<<1, 256>>>(Wrel1, b1, Wroot1, Wrel2, b2, Wroot2,
                            Wg1, bg1, Wg2, bg2, Wg3, bg3);
    gnn_kernel<<<GNN_GRID, 128>>>(x, ei, ea, gfeats);
    mlp_kernel<<<BGRAPH / 32, 256>>>(Wo1, bo1, Wo2, bo2, out);
}